// round 7
// baseline (speedup 1.0000x reference)
#include <cuda_runtime.h>
#include <math.h>

// Problem shape (fixed by the reference)
#define NSAMP 2048
#define OBS   48
// Layers: (out, in)
// L0: 512 x 48   L1: 256 x 512   L2: 128 x 256   L3: 12 x 128

// Inter-layer activation scratch (device globals: allocation-free).
__device__ __align__(16) float g_a0[NSAMP * 512];
__device__ __align__(16) float g_a1[NSAMP * 256];

__device__ __forceinline__ float elu(float s) {
    return (s > 0.0f) ? s : (__expf(s) - 1.0f);
}

// ---------------------------------------------------------------------------
// L0: obs-norm fused with 512x48 layer. 256 threads, 128 rows/CTA
// -> 4 CTAs/sample. Weights staged through smem as a flat coalesced float4
// stream (6 loads/thread, MLP=6, all lanes active); dots computed from smem.
// ---------------------------------------------------------------------------
#define L0_ROWS 128
__global__ void __launch_bounds__(256, 8)
k_l0(const float* __restrict__ obs, const float* __restrict__ mean,
     const float* __restrict__ stdv, const float* __restrict__ W0,
     const float* __restrict__ b0) {
    const int b  = blockIdx.x;
    const int n  = b >> 2;             // sample
    const int rb = (b & 3) * L0_ROWS;  // row base within sample
    const int tid = threadIdx.x;

    __shared__ __align__(16) float xs[OBS];
    __shared__ __align__(16) float ws[L0_ROWS * 48];   // 24 KB

    // Stage 128 rows of weights: 1536 float4, perfectly coalesced.
    {
        const float4* __restrict__ src = reinterpret_cast<const float4*>(
            W0 + (size_t)n * 512 * 48 + (size_t)rb * 48);
        float4* dst = reinterpret_cast<float4*>(ws);
        #pragma unroll
        for (int i = 0; i < 6; i++)
            dst[tid + 256 * i] = __ldcs(src + tid + 256 * i);
    }
    if (tid < OBS) {
        const int i = n * OBS + tid;
        float v = (obs[i] - mean[i]) / stdv[i];
        xs[tid] = fminf(fmaxf(v, -5.0f), 5.0f);
    }
    __syncthreads();

    const int gid = tid >> 4;          // 16 groups of 16 lanes
    const int gl  = tid & 15;
    const float* __restrict__ bb = b0 + (size_t)n * 512 + rb;
    float* __restrict__ y = g_a0 + (size_t)n * 512 + rb;

    float4 v = make_float4(0.f, 0.f, 0.f, 0.f);
    if (gl < 12) v = reinterpret_cast<const float4*>(xs)[gl];

    // Rows for this group: gid + 16k, k = 0..7, processed 4 at a time.
    #pragma unroll
    for (int k = 0; k < 8; k += 4) {
        int r[4];
        float s[4];
        #pragma unroll
        for (int u = 0; u < 4; u++) {
            r[u] = gid + 16 * (k + u);
            s[u] = 0.0f;
        }
        float bias[4];
        #pragma unroll
        for (int u = 0; u < 4; u++) bias[u] = __ldcs(bb + r[u]);
        if (gl < 12) {
            #pragma unroll
            for (int u = 0; u < 4; u++) {
                const float4* __restrict__ Wr =
                    reinterpret_cast<const float4*>(ws + r[u] * 48);
                float4 w = Wr[gl];
                s[u] = fmaf(w.x, v.x,
                        fmaf(w.y, v.y, fmaf(w.z, v.z, w.w * v.w)));
            }
        }
        #pragma unroll
        for (int o = 8; o >= 1; o >>= 1) {
            #pragma unroll
            for (int u = 0; u < 4; u++)
                s[u] += __shfl_xor_sync(0xffffffffu, s[u], o);
        }
        if (gl == 0) {
            #pragma unroll
            for (int u = 0; u < 4; u++)
                y[r[u]] = elu(s[u] + bias[u]);
        }
    }
}

// ---------------------------------------------------------------------------
// L1: 256 x 512. 256 threads (8 warps), warp per row-pair, 32 rows/CTA
// -> 8 CTAs per sample.
// ---------------------------------------------------------------------------
__global__ void __launch_bounds__(256, 8)
k_l1(const float* __restrict__ Wg, const float* __restrict__ bg,
     const float* __restrict__ xg, float* __restrict__ yg) {
    constexpr int IN = 512, NV = IN / 4;
    const int b  = blockIdx.x;
    const int n  = b >> 3;
    const int rb = (b & 7) * 32;
    const int tid = threadIdx.x;
    const int wid = tid >> 5;          // 8 warps
    const int gl  = tid & 31;

    __shared__ __align__(16) float xs[IN];
    {
        const float4* __restrict__ src =
            reinterpret_cast<const float4*>(xg + (size_t)n * IN);
        if (tid < NV) reinterpret_cast<float4*>(xs)[tid] = src[tid];
    }
    __syncthreads();

    const float4* __restrict__ xv = reinterpret_cast<const float4*>(xs);
    const float* __restrict__ W = Wg + (size_t)n * 256 * IN;
    const float* __restrict__ bb = bg + (size_t)n * 256;
    float* __restrict__ y = yg + (size_t)n * 256;

    #pragma unroll
    for (int r0 = rb + wid; r0 < rb + 32; r0 += 16) {
        const int r1 = r0 + 8;
        float bias0 = __ldcs(bb + r0);
        float bias1 = __ldcs(bb + r1);
        const float4* __restrict__ Wr0 =
            reinterpret_cast<const float4*>(W + (size_t)r0 * IN);
        const float4* __restrict__ Wr1 =
            reinterpret_cast<const float4*>(W + (size_t)r1 * IN);
        float s0 = 0.0f, s1 = 0.0f;
        #pragma unroll
        for (int j = gl; j < NV; j += 32) {
            float4 w0 = __ldcs(Wr0 + j);
            float4 w1 = __ldcs(Wr1 + j);
            float4 v  = xv[j];
            s0 = fmaf(w0.x, v.x, s0);
            s0 = fmaf(w0.y, v.y, s0);
            s0 = fmaf(w0.z, v.z, s0);
            s0 = fmaf(w0.w, v.w, s0);
            s1 = fmaf(w1.x, v.x, s1);
            s1 = fmaf(w1.y, v.y, s1);
            s1 = fmaf(w1.z, v.z, s1);
            s1 = fmaf(w1.w, v.w, s1);
        }
        #pragma unroll
        for (int o = 16; o >= 1; o >>= 1) {
            s0 += __shfl_xor_sync(0xffffffffu, s0, o);
            s1 += __shfl_xor_sync(0xffffffffu, s1, o);
        }
        if (gl == 0) {
            y[r0] = elu(s0 + bias0);
            y[r1] = elu(s1 + bias1);
        }
    }
}

// ---------------------------------------------------------------------------
// L2 (128x256) fused with L3 (12x128) + tanh. One CTA (128 thr) per sample.
// L2 uses 4 rows per warp-iteration for deeper load pipelining.
// ---------------------------------------------------------------------------
__global__ void __launch_bounds__(128, 16)
k_l23(const float* __restrict__ W2, const float* __restrict__ b2,
      const float* __restrict__ W3, const float* __restrict__ b3,
      float* __restrict__ out) {
    constexpr int IN2 = 256, NV2 = IN2 / 4;   // 64
    const int n = blockIdx.x;
    const int tid = threadIdx.x;
    const int wid = tid >> 5;          // 4 warps
    const int gl  = tid & 31;

    __shared__ __align__(16) float xs[IN2];
    __shared__ __align__(16) float h[128];
    {
        const float4* __restrict__ src =
            reinterpret_cast<const float4*>(g_a1 + (size_t)n * IN2);
        if (tid < NV2) reinterpret_cast<float4*>(xs)[tid] = src[tid];
    }
    __syncthreads();

    // ---- L2: 128 rows, 4 rows per warp-iteration ----
    {
        const float4* __restrict__ xv = reinterpret_cast<const float4*>(xs);
        const float* __restrict__ W = W2 + (size_t)n * 128 * IN2;
        const float* __restrict__ bb = b2 + (size_t)n * 128;
        #pragma unroll
        for (int base = wid; base < 128; base += 16) {
            int r[4];
            float bias[4], s[4];
            #pragma unroll
            for (int u = 0; u < 4; u++) {
                r[u] = base + 4 * u;
                bias[u] = __ldcs(bb + r[u]);
                s[u] = 0.0f;
            }
            const float4* Wr[4];
            #pragma unroll
            for (int u = 0; u < 4; u++)
                Wr[u] = reinterpret_cast<const float4*>(W + (size_t)r[u] * IN2);
            #pragma unroll
            for (int j = gl; j < NV2; j += 32) {
                float4 v = xv[j];
                #pragma unroll
                for (int u = 0; u < 4; u++) {
                    float4 w = __ldcs(Wr[u] + j);
                    s[u] = fmaf(w.x, v.x, s[u]);
                    s[u] = fmaf(w.y, v.y, s[u]);
                    s[u] = fmaf(w.z, v.z, s[u]);
                    s[u] = fmaf(w.w, v.w, s[u]);
                }
            }
            #pragma unroll
            for (int o = 16; o >= 1; o >>= 1) {
                #pragma unroll
                for (int u = 0; u < 4; u++)
                    s[u] += __shfl_xor_sync(0xffffffffu, s[u], o);
            }
            if (gl == 0) {
                #pragma unroll
                for (int u = 0; u < 4; u++)
                    h[r[u]] = elu(s[u] + bias[u]);
            }
        }
    }
    __syncthreads();

    // ---- L3: 12 x 128 + tanh ----
    {
        const float4* __restrict__ hv = reinterpret_cast<const float4*>(h);
        const float* __restrict__ W = W3 + (size_t)n * 12 * 128;
        const float* __restrict__ bb = b3 + (size_t)n * 12;
        #pragma unroll
        for (int row = wid; row < 12; row += 4) {
            float bias = __ldcs(bb + row);
            const float4* __restrict__ Wr =
                reinterpret_cast<const float4*>(W + (size_t)row * 128);
            float4 w = __ldcs(Wr + gl);
            float4 v = hv[gl];
            float s = fmaf(w.x, v.x, fmaf(w.y, v.y, fmaf(w.z, v.z, w.w * v.w)));
            #pragma unroll
            for (int o = 16; o >= 1; o >>= 1)
                s += __shfl_xor_sync(0xffffffffu, s, o);
            if (gl == 0)
                out[n * 12 + row] = tanhf(s + bias);
        }
    }
}

extern "C" void kernel_launch(void* const* d_in, const int* in_sizes, int n_in,
                              void* d_out, int out_size) {
    const float* obs  = (const float*)d_in[0];
    const float* mean = (const float*)d_in[1];
    const float* stdv = (const float*)d_in[2];
    const float* W0   = (const float*)d_in[3];
    const float* b0   = (const float*)d_in[4];
    const float* W1   = (const float*)d_in[5];
    const float* b1   = (const float*)d_in[6];
    const float* W2   = (const float*)d_in[7];
    const float* b2   = (const float*)d_in[8];
    const float* W3   = (const float*)d_in[9];
    const float* b3   = (const float*)d_in[10];
    float* out = (float*)d_out;

    float* a0;  cudaGetSymbolAddress((void**)&a0, g_a0);
    float* a1;  cudaGetSymbolAddress((void**)&a1, g_a1);

    // L0: 4 CTAs/sample (smem-staged weights)
    k_l0<<<NSAMP * 4, 256>>>(obs, mean, stdv, W0, b0);
    // L1: 8 CTAs/sample
    k_l1<<<NSAMP * 8, 256>>>(W1, b1, a0, a1);
    // L2+L3 fused: 1 CTA/sample
    k_l23<<<NSAMP, 128>>>(W2, b2, W3, b3, out);
}

// round 8
// speedup vs baseline: 1.0791x; 1.0791x over previous
#include <cuda_runtime.h>
#include <math.h>

// Problem shape (fixed by the reference)
#define NSAMP 2048
#define OBS   48
// Layers: (out, in)
// L0: 512 x 48   L1: 256 x 512   L2: 128 x 256   L3: 12 x 128

// Inter-layer activation scratch (device globals: allocation-free).
__device__ __align__(16) float g_a0[NSAMP * 512];
__device__ __align__(16) float g_a1[NSAMP * 256];
__device__ __align__(16) float g_a2[NSAMP * 128];

__device__ __forceinline__ float elu(float s) {
    return (s > 0.0f) ? s : (__expf(s) - 1.0f);
}

// ---------------------------------------------------------------------------
// L0: obs-norm fused with 512x48 layer. 4-lane groups: lane gl loads 3
// contiguous float4 of one row; warp covers 8 rows = 1536B fully coalesced;
// 2-deep row-batch unroll -> 6 independent loads/lane; 2 shuffle rounds only.
// 256 threads, 128 rows/CTA -> 4 CTAs/sample (grid 8192).
// ---------------------------------------------------------------------------
__global__ void __launch_bounds__(256)
k_l0(const float* __restrict__ obs, const float* __restrict__ mean,
     const float* __restrict__ stdv, const float* __restrict__ W0,
     const float* __restrict__ b0) {
    const int b  = blockIdx.x;
    const int n  = b >> 2;             // sample
    const int rb = (b & 3) * 128;      // row base within sample
    const int tid = threadIdx.x;

    __shared__ __align__(16) float xs[OBS];
    if (tid < OBS) {
        const int i = n * OBS + tid;
        float v = (obs[i] - mean[i]) / stdv[i];
        xs[tid] = fminf(fmaxf(v, -5.0f), 5.0f);
    }
    __syncthreads();

    const int wid  = tid >> 5;         // 8 warps
    const int lane = tid & 31;
    const int g    = lane >> 2;        // 8 row-groups per warp
    const int gl   = lane & 3;         // 4 lanes per row

    // x segments for this lane (registers; conflict-free broadcast reads)
    const float4* __restrict__ xv = reinterpret_cast<const float4*>(xs);
    const float4 v0 = xv[gl * 3 + 0];
    const float4 v1 = xv[gl * 3 + 1];
    const float4 v2 = xv[gl * 3 + 2];

    const float* __restrict__ W  = W0 + (size_t)n * 512 * 48;
    const float* __restrict__ bb = b0 + (size_t)n * 512;
    float* __restrict__ y = g_a0 + (size_t)n * 512;

    // Warp covers rows [rb + wid*16, rb + wid*16 + 16), two 8-row batches.
    const int r0 = rb + wid * 16 + g;
    const int r1 = r0 + 8;

    const float4* __restrict__ Wr0 =
        reinterpret_cast<const float4*>(W + (size_t)r0 * 48) + gl * 3;
    const float4* __restrict__ Wr1 =
        reinterpret_cast<const float4*>(W + (size_t)r1 * 48) + gl * 3;

    float bias0 = 0.f, bias1 = 0.f;
    if (gl == 0) { bias0 = __ldcs(bb + r0); bias1 = __ldcs(bb + r1); }

    float4 a0 = __ldcs(Wr0 + 0), a1 = __ldcs(Wr0 + 1), a2 = __ldcs(Wr0 + 2);
    float4 c0 = __ldcs(Wr1 + 0), c1 = __ldcs(Wr1 + 1), c2 = __ldcs(Wr1 + 2);

    float s0 = fmaf(a0.x, v0.x, fmaf(a0.y, v0.y, fmaf(a0.z, v0.z, a0.w * v0.w)));
    s0 = fmaf(a1.x, v1.x, fmaf(a1.y, v1.y, fmaf(a1.z, v1.z, fmaf(a1.w, v1.w, s0))));
    s0 = fmaf(a2.x, v2.x, fmaf(a2.y, v2.y, fmaf(a2.z, v2.z, fmaf(a2.w, v2.w, s0))));
    float s1 = fmaf(c0.x, v0.x, fmaf(c0.y, v0.y, fmaf(c0.z, v0.z, c0.w * v0.w)));
    s1 = fmaf(c1.x, v1.x, fmaf(c1.y, v1.y, fmaf(c1.z, v1.z, fmaf(c1.w, v1.w, s1))));
    s1 = fmaf(c2.x, v2.x, fmaf(c2.y, v2.y, fmaf(c2.z, v2.z, fmaf(c2.w, v2.w, s1))));

    // reduce across the 4 lanes of each group
    s0 += __shfl_xor_sync(0xffffffffu, s0, 1);
    s1 += __shfl_xor_sync(0xffffffffu, s1, 1);
    s0 += __shfl_xor_sync(0xffffffffu, s0, 2);
    s1 += __shfl_xor_sync(0xffffffffu, s1, 2);

    if (gl == 0) {
        y[r0] = elu(s0 + bias0);
        y[r1] = elu(s1 + bias1);
    }
}

// ---------------------------------------------------------------------------
// Generic hidden layer: OUT x IN, warp per row-pair, ROWS_PER_CTA rows/CTA.
// 256 threads = 8 warps -> 16 rows per pass.
// ---------------------------------------------------------------------------
template <int OUT, int IN, int ROWS_PER_CTA, bool ACT>
__global__ void __launch_bounds__(256, 8)
k_layer(const float* __restrict__ Wg, const float* __restrict__ bg,
        const float* __restrict__ xg, float* __restrict__ yg) {
    constexpr int CTAS_PER_SAMPLE = OUT / ROWS_PER_CTA;
    constexpr int NV = IN / 4;
    const int b  = blockIdx.x;
    const int n  = b / CTAS_PER_SAMPLE;
    const int rb = (b % CTAS_PER_SAMPLE) * ROWS_PER_CTA;
    const int tid = threadIdx.x;
    const int wid = tid >> 5;          // 8 warps
    const int gl  = tid & 31;

    __shared__ __align__(16) float xs[IN];
    {
        const float4* __restrict__ src =
            reinterpret_cast<const float4*>(xg + (size_t)n * IN);
        if (tid < NV) reinterpret_cast<float4*>(xs)[tid] = src[tid];
    }
    __syncthreads();

    const float4* __restrict__ xv = reinterpret_cast<const float4*>(xs);
    const float* __restrict__ W = Wg + (size_t)n * OUT * IN;
    const float* __restrict__ bb = bg + (size_t)n * OUT;
    float* __restrict__ y = yg + (size_t)n * OUT;

    #pragma unroll
    for (int r0 = rb + wid; r0 < rb + ROWS_PER_CTA; r0 += 16) {
        const int r1 = r0 + 8;
        float bias0 = __ldcs(bb + r0);
        float bias1 = __ldcs(bb + r1);
        const float4* __restrict__ Wr0 =
            reinterpret_cast<const float4*>(W + (size_t)r0 * IN);
        const float4* __restrict__ Wr1 =
            reinterpret_cast<const float4*>(W + (size_t)r1 * IN);
        float s0 = 0.0f, s1 = 0.0f;
        #pragma unroll
        for (int j = gl; j < NV; j += 32) {
            float4 w0 = __ldcs(Wr0 + j);
            float4 w1 = __ldcs(Wr1 + j);
            float4 v  = xv[j];
            s0 = fmaf(w0.x, v.x, s0);
            s0 = fmaf(w0.y, v.y, s0);
            s0 = fmaf(w0.z, v.z, s0);
            s0 = fmaf(w0.w, v.w, s0);
            s1 = fmaf(w1.x, v.x, s1);
            s1 = fmaf(w1.y, v.y, s1);
            s1 = fmaf(w1.z, v.z, s1);
            s1 = fmaf(w1.w, v.w, s1);
        }
        #pragma unroll
        for (int o = 16; o >= 1; o >>= 1) {
            s0 += __shfl_xor_sync(0xffffffffu, s0, o);
            s1 += __shfl_xor_sync(0xffffffffu, s1, o);
        }
        if (gl == 0) {
            s0 += bias0;
            s1 += bias1;
            if (ACT) { s0 = elu(s0); s1 = elu(s1); }
            y[r0] = s0;
            y[r1] = s1;
        }
    }
}

// ---------------------------------------------------------------------------
// L3: 12 x 128 + tanh. One CTA (128 threads = 4 warps) per sample.
// ---------------------------------------------------------------------------
__global__ void __launch_bounds__(128, 16)
k_l3(const float* __restrict__ W3, const float* __restrict__ b3,
     float* __restrict__ out) {
    const int n = blockIdx.x;
    const int tid = threadIdx.x;
    const int wid = tid >> 5;
    const int gl  = tid & 31;

    __shared__ __align__(16) float xs[128];
    {
        const float4* __restrict__ src =
            reinterpret_cast<const float4*>(g_a2 + (size_t)n * 128);
        if (tid < 32) reinterpret_cast<float4*>(xs)[tid] = src[tid];
    }
    __syncthreads();

    const float4* __restrict__ xv = reinterpret_cast<const float4*>(xs);
    const float* __restrict__ W = W3 + (size_t)n * 12 * 128;
    const float* __restrict__ bb = b3 + (size_t)n * 12;

    #pragma unroll
    for (int row = wid; row < 12; row += 4) {
        float bias = __ldcs(bb + row);
        const float4* __restrict__ Wr =
            reinterpret_cast<const float4*>(W + (size_t)row * 128);
        float4 w = __ldcs(Wr + gl);
        float4 v = xv[gl];
        float s = fmaf(w.x, v.x, fmaf(w.y, v.y, fmaf(w.z, v.z, w.w * v.w)));
        #pragma unroll
        for (int o = 16; o >= 1; o >>= 1)
            s += __shfl_xor_sync(0xffffffffu, s, o);
        if (gl == 0)
            out[n * 12 + row] = tanhf(s + bias);
    }
}

extern "C" void kernel_launch(void* const* d_in, const int* in_sizes, int n_in,
                              void* d_out, int out_size) {
    const float* obs  = (const float*)d_in[0];
    const float* mean = (const float*)d_in[1];
    const float* stdv = (const float*)d_in[2];
    const float* W0   = (const float*)d_in[3];
    const float* b0   = (const float*)d_in[4];
    const float* W1   = (const float*)d_in[5];
    const float* b1   = (const float*)d_in[6];
    const float* W2   = (const float*)d_in[7];
    const float* b2   = (const float*)d_in[8];
    const float* W3   = (const float*)d_in[9];
    const float* b3   = (const float*)d_in[10];
    float* out = (float*)d_out;

    float* a0;  cudaGetSymbolAddress((void**)&a0, g_a0);
    float* a1;  cudaGetSymbolAddress((void**)&a1, g_a1);
    float* a2;  cudaGetSymbolAddress((void**)&a2, g_a2);

    // L0: 4 CTAs/sample (4-lane-group streaming)
    k_l0<<<NSAMP * 4, 256>>>(obs, mean, stdv, W0, b0);
    // L1: 256x512, 32 rows/CTA -> 8 CTAs/sample
    k_layer<256, 512, 32, true><<<NSAMP * 8, 256>>>(W1, b1, a0, a1);
    // L2: 128x256, 16 rows/CTA -> 8 CTAs/sample
    k_layer<128, 256, 16, true><<<NSAMP * 8, 256>>>(W2, b2, a1, a2);
    // L3: 12x128 + tanh, 1 CTA/sample
    k_l3<<<NSAMP, 128>>>(W3, b3, out);
}

// round 9
// speedup vs baseline: 1.0884x; 1.0087x over previous
#include <cuda_runtime.h>
#include <math.h>

// Problem shape (fixed by the reference)
#define NSAMP 2048
#define OBS   48
// Layers: (out, in)
// L0: 512 x 48   L1: 256 x 512   L2: 128 x 256   L3: 12 x 128

// Inter-layer activation scratch (device globals: allocation-free).
__device__ __align__(16) float g_a0[NSAMP * 512];
__device__ __align__(16) float g_a1[NSAMP * 256];
__device__ __align__(16) float g_a2[NSAMP * 128];

__device__ __forceinline__ float elu(float s) {
    return (s > 0.0f) ? s : (__expf(s) - 1.0f);
}

// ---------------------------------------------------------------------------
// L0: obs-norm fused with 512x48 layer. 4-lane groups: lane gl loads 3
// contiguous float4 of one row; warp covers 8 rows = 1536B fully coalesced;
// 2-deep row-batch unroll -> 6 independent loads/lane; 2 shuffle rounds only.
// 256 threads, 128 rows/CTA -> 4 CTAs/sample (grid 8192).
// ---------------------------------------------------------------------------
__global__ void __launch_bounds__(256)
k_l0(const float* __restrict__ obs, const float* __restrict__ mean,
     const float* __restrict__ stdv, const float* __restrict__ W0,
     const float* __restrict__ b0) {
    const int b  = blockIdx.x;
    const int n  = b >> 2;             // sample
    const int rb = (b & 3) * 128;      // row base within sample
    const int tid = threadIdx.x;

    __shared__ __align__(16) float xs[OBS];
    if (tid < OBS) {
        const int i = n * OBS + tid;
        float v = (obs[i] - mean[i]) / stdv[i];
        xs[tid] = fminf(fmaxf(v, -5.0f), 5.0f);
    }
    __syncthreads();

    const int wid  = tid >> 5;         // 8 warps
    const int lane = tid & 31;
    const int g    = lane >> 2;        // 8 row-groups per warp
    const int gl   = lane & 3;         // 4 lanes per row

    const float4* __restrict__ xv = reinterpret_cast<const float4*>(xs);
    const float4 v0 = xv[gl * 3 + 0];
    const float4 v1 = xv[gl * 3 + 1];
    const float4 v2 = xv[gl * 3 + 2];

    const float* __restrict__ W  = W0 + (size_t)n * 512 * 48;
    const float* __restrict__ bb = b0 + (size_t)n * 512;
    float* __restrict__ y = g_a0 + (size_t)n * 512;

    const int r0 = rb + wid * 16 + g;
    const int r1 = r0 + 8;

    const float4* __restrict__ Wr0 =
        reinterpret_cast<const float4*>(W + (size_t)r0 * 48) + gl * 3;
    const float4* __restrict__ Wr1 =
        reinterpret_cast<const float4*>(W + (size_t)r1 * 48) + gl * 3;

    float bias0 = 0.f, bias1 = 0.f;
    if (gl == 0) { bias0 = __ldcs(bb + r0); bias1 = __ldcs(bb + r1); }

    float4 a0 = __ldcs(Wr0 + 0), a1 = __ldcs(Wr0 + 1), a2 = __ldcs(Wr0 + 2);
    float4 c0 = __ldcs(Wr1 + 0), c1 = __ldcs(Wr1 + 1), c2 = __ldcs(Wr1 + 2);

    float s0 = fmaf(a0.x, v0.x, fmaf(a0.y, v0.y, fmaf(a0.z, v0.z, a0.w * v0.w)));
    s0 = fmaf(a1.x, v1.x, fmaf(a1.y, v1.y, fmaf(a1.z, v1.z, fmaf(a1.w, v1.w, s0))));
    s0 = fmaf(a2.x, v2.x, fmaf(a2.y, v2.y, fmaf(a2.z, v2.z, fmaf(a2.w, v2.w, s0))));
    float s1 = fmaf(c0.x, v0.x, fmaf(c0.y, v0.y, fmaf(c0.z, v0.z, c0.w * v0.w)));
    s1 = fmaf(c1.x, v1.x, fmaf(c1.y, v1.y, fmaf(c1.z, v1.z, fmaf(c1.w, v1.w, s1))));
    s1 = fmaf(c2.x, v2.x, fmaf(c2.y, v2.y, fmaf(c2.z, v2.z, fmaf(c2.w, v2.w, s1))));

    s0 += __shfl_xor_sync(0xffffffffu, s0, 1);
    s1 += __shfl_xor_sync(0xffffffffu, s1, 1);
    s0 += __shfl_xor_sync(0xffffffffu, s0, 2);
    s1 += __shfl_xor_sync(0xffffffffu, s1, 2);

    if (gl == 0) {
        y[r0] = elu(s0 + bias0);
        y[r1] = elu(s1 + bias1);
    }
}

// ---------------------------------------------------------------------------
// Generic hidden layer: OUT x IN, warp per row-pair, ROWS_PER_CTA rows/CTA.
// 256 threads = 8 warps -> 16 rows per pass.
// ---------------------------------------------------------------------------
template <int OUT, int IN, int ROWS_PER_CTA, bool ACT>
__global__ void __launch_bounds__(256, 8)
k_layer(const float* __restrict__ Wg, const float* __restrict__ bg,
        const float* __restrict__ xg, float* __restrict__ yg) {
    constexpr int CTAS_PER_SAMPLE = OUT / ROWS_PER_CTA;
    constexpr int NV = IN / 4;
    const int b  = blockIdx.x;
    const int n  = b / CTAS_PER_SAMPLE;
    const int rb = (b % CTAS_PER_SAMPLE) * ROWS_PER_CTA;
    const int tid = threadIdx.x;
    const int wid = tid >> 5;          // 8 warps
    const int gl  = tid & 31;

    __shared__ __align__(16) float xs[IN];
    {
        const float4* __restrict__ src =
            reinterpret_cast<const float4*>(xg + (size_t)n * IN);
        if (tid < NV) reinterpret_cast<float4*>(xs)[tid] = src[tid];
    }
    __syncthreads();

    const float4* __restrict__ xv = reinterpret_cast<const float4*>(xs);
    const float* __restrict__ W = Wg + (size_t)n * OUT * IN;
    const float* __restrict__ bb = bg + (size_t)n * OUT;
    float* __restrict__ y = yg + (size_t)n * OUT;

    #pragma unroll
    for (int r0 = rb + wid; r0 < rb + ROWS_PER_CTA; r0 += 16) {
        const int r1 = r0 + 8;
        float bias0 = __ldcs(bb + r0);
        float bias1 = __ldcs(bb + r1);
        const float4* __restrict__ Wr0 =
            reinterpret_cast<const float4*>(W + (size_t)r0 * IN);
        const float4* __restrict__ Wr1 =
            reinterpret_cast<const float4*>(W + (size_t)r1 * IN);
        float s0 = 0.0f, s1 = 0.0f;
        #pragma unroll
        for (int j = gl; j < NV; j += 32) {
            float4 w0 = __ldcs(Wr0 + j);
            float4 w1 = __ldcs(Wr1 + j);
            float4 v  = xv[j];
            s0 = fmaf(w0.x, v.x, s0);
            s0 = fmaf(w0.y, v.y, s0);
            s0 = fmaf(w0.z, v.z, s0);
            s0 = fmaf(w0.w, v.w, s0);
            s1 = fmaf(w1.x, v.x, s1);
            s1 = fmaf(w1.y, v.y, s1);
            s1 = fmaf(w1.z, v.z, s1);
            s1 = fmaf(w1.w, v.w, s1);
        }
        #pragma unroll
        for (int o = 16; o >= 1; o >>= 1) {
            s0 += __shfl_xor_sync(0xffffffffu, s0, o);
            s1 += __shfl_xor_sync(0xffffffffu, s1, o);
        }
        if (gl == 0) {
            s0 += bias0;
            s1 += bias1;
            if (ACT) { s0 = elu(s0); s1 = elu(s1); }
            y[r0] = s0;
            y[r1] = s1;
        }
    }
}

// ---------------------------------------------------------------------------
// L3: 12 x 128 + tanh. One WARP per sample; 256-thread CTAs -> 8 samples/CTA,
// grid = 256. Lane j holds x float4 j; 12 independent W-row loads per lane.
// No shared memory, no __syncthreads.
// ---------------------------------------------------------------------------
__global__ void __launch_bounds__(256)
k_l3(const float* __restrict__ W3, const float* __restrict__ b3,
     float* __restrict__ out) {
    const int tid  = threadIdx.x;
    const int lane = tid & 31;
    const int n    = blockIdx.x * 8 + (tid >> 5);   // sample for this warp

    const float4* __restrict__ xv =
        reinterpret_cast<const float4*>(g_a2 + (size_t)n * 128);
    const float4* __restrict__ Wv =
        reinterpret_cast<const float4*>(W3 + (size_t)n * 12 * 128);

    // bias for this lane's output row (lanes 0..11)
    float bias = (lane < 12) ? __ldcs(b3 + n * 12 + lane) : 0.0f;

    float4 v = xv[lane];

    float s[12];
    #pragma unroll
    for (int r = 0; r < 12; r++) {
        float4 w = __ldcs(Wv + r * 32 + lane);
        s[r] = fmaf(w.x, v.x, fmaf(w.y, v.y, fmaf(w.z, v.z, w.w * v.w)));
    }
    #pragma unroll
    for (int o = 16; o >= 1; o >>= 1) {
        #pragma unroll
        for (int r = 0; r < 12; r++)
            s[r] += __shfl_xor_sync(0xffffffffu, s[r], o);
    }

    // lane r writes output row r
    float mine = 0.0f;
    #pragma unroll
    for (int r = 0; r < 12; r++)
        if (lane == r) mine = s[r];
    if (lane < 12)
        out[n * 12 + lane] = tanhf(mine + bias);
}

extern "C" void kernel_launch(void* const* d_in, const int* in_sizes, int n_in,
                              void* d_out, int out_size) {
    const float* obs  = (const float*)d_in[0];
    const float* mean = (const float*)d_in[1];
    const float* stdv = (const float*)d_in[2];
    const float* W0   = (const float*)d_in[3];
    const float* b0   = (const float*)d_in[4];
    const float* W1   = (const float*)d_in[5];
    const float* b1   = (const float*)d_in[6];
    const float* W2   = (const float*)d_in[7];
    const float* b2   = (const float*)d_in[8];
    const float* W3   = (const float*)d_in[9];
    const float* b3   = (const float*)d_in[10];
    float* out = (float*)d_out;

    float* a0;  cudaGetSymbolAddress((void**)&a0, g_a0);
    float* a1;  cudaGetSymbolAddress((void**)&a1, g_a1);
    float* a2;  cudaGetSymbolAddress((void**)&a2, g_a2);

    // L0: 4 CTAs/sample (4-lane-group streaming)
    k_l0<<<NSAMP * 4, 256>>>(obs, mean, stdv, W0, b0);
    // L1: 256x512, 32 rows/CTA -> 8 CTAs/sample
    k_layer<256, 512, 32, true><<<NSAMP * 8, 256>>>(W1, b1, a0, a1);
    // L2: 128x256, 16 rows/CTA -> 8 CTAs/sample
    k_layer<128, 256, 16, true><<<NSAMP * 8, 256>>>(W2, b2, a1, a2);
    // L3: 12x128 + tanh, warp/sample, 8 samples/CTA
    k_l3<<<NSAMP / 8, 256>>>(W3, b3, out);
}